// round 17
// baseline (speedup 1.0000x reference)
#include <cuda_runtime.h>
#include <cuda_fp16.h>
#include <cstdint>

#define WS    8
#define MQ    4
#define HEADS 8
#define DIM   256
#define HD    32
#define BATCH 4
#define IMGH  128
#define IMGW  128
#define NWIN  256
#define BW    (BATCH*NWIN)   // 1024 windows
#define WS2   64
#define NQ    (MQ*WS2)       // 256
#define ROWS_Q  (BW*NQ)      // 262144
#define ROWS_KV (BW*WS2)     // 65536

__device__ __half g_q   [ROWS_Q  * DIM];
__device__ __half g_kv  [ROWS_KV * 2 * DIM];
__device__ __half g_att [ROWS_Q  * DIM];
__device__ __half g_bias[HEADS * WS2 * WS2];     // [h][q][k] fp16
// transposed fp16 weights, [n][k] k-contiguous: wq [0,256) wkv [256,768) wp [768,1024)
__device__ __half g_wt  [1024 * DIM];

__device__ __forceinline__ uint32_t pkh2(float a, float b) {
    __half2 h = __floats2half2_rn(a, b);
    return *(uint32_t*)&h;
}
__device__ __forceinline__ void mma_f16(float c[4],
    uint32_t a0, uint32_t a1, uint32_t a2, uint32_t a3,
    uint32_t b0, uint32_t b1)
{
    asm volatile(
        "mma.sync.aligned.m16n8k16.row.col.f32.f16.f16.f32 "
        "{%0,%1,%2,%3}, {%4,%5,%6,%7}, {%8,%9}, {%0,%1,%2,%3};"
        : "+f"(c[0]), "+f"(c[1]), "+f"(c[2]), "+f"(c[3])
        : "r"(a0), "r"(a1), "r"(a2), "r"(a3), "r"(b0), "r"(b1));
}
__device__ __forceinline__ void ldsm_x4(uint32_t& r0, uint32_t& r1,
                                        uint32_t& r2, uint32_t& r3, uint32_t addr)
{
    asm volatile("ldmatrix.sync.aligned.m8n8.x4.shared.b16 {%0,%1,%2,%3}, [%4];"
                 : "=r"(r0), "=r"(r1), "=r"(r2), "=r"(r3) : "r"(addr));
}
__device__ __forceinline__ void ldsm_x4_t(uint32_t& r0, uint32_t& r1,
                                          uint32_t& r2, uint32_t& r3, uint32_t addr)
{
    asm volatile("ldmatrix.sync.aligned.m8n8.x4.trans.shared.b16 {%0,%1,%2,%3}, [%4];"
                 : "=r"(r0), "=r"(r1), "=r"(r2), "=r"(r3) : "r"(addr));
}
#define CP_ASYNC16(dst, src) \
    asm volatile("cp.async.ca.shared.global [%0], [%1], 16;" :: "r"(dst), "l"(src) : "memory")
#define CP_COMMIT()  asm volatile("cp.async.commit_group;" ::: "memory")
#define CP_WAIT1()   asm volatile("cp.async.wait_group 1;" ::: "memory")
#define CP_WAIT0()   asm volatile("cp.async.wait_group 0;" ::: "memory")

// ---------------------------------------------------------------------------
// prep kernels
// ---------------------------------------------------------------------------
__global__ void bias_prep_kernel(const float* __restrict__ btab)
{
    const int h = blockIdx.x;
    const int t = threadIdx.x;
    #pragma unroll
    for (int i = 0; i < 16; i++) {
        int e  = t + i * 256;
        int qp = e >> 6, kp = e & 63;
        int dr = (qp >> 3) - (kp >> 3) + 7;
        int dc = (qp & 7)  - (kp & 7)  + 7;
        g_bias[h * 4096 + e] = __float2half(btab[(dr * 15 + dc) * HEADS + h]);
    }
}
__global__ void w_prep_kernel(const float* __restrict__ Wq,
                              const float* __restrict__ Wkv,
                              const float* __restrict__ Wp)
{
    const int idx = blockIdx.x * 256 + threadIdx.x;
    const int row = idx >> 8;
    const int k   = idx & 255;
    float v;
    if (row < 256)       v = Wq [(size_t)k * 256 + row];
    else if (row < 768)  v = Wkv[(size_t)k * 512 + (row - 256)];
    else                 v = Wp [(size_t)k * 256 + (row - 768)];
    g_wt[idx] = __float2half(v);
}

// ---------------------------------------------------------------------------
// fp16 GEMM (fp32 accum): C[M,N] = A[M,256] @ W[256,N] + bias[N]
// Block 256x128, BK=32, 512 threads = 16 warps (8x2), warp tile 32x64.
// Dynamic smem: W 3-slot ring (3x8KB) + A 3-slot (3x16KB) = 72KB, 1 CTA/SM
// (16 warps/SM, same as 2x256 before). W staged via cp.async; A via
// cp.async (AHALF) or reg path (fp32 convert).
// ---------------------------------------------------------------------------
#define GEMM_SMEM (24576 + 49152 + 128)

template<bool GATHER, bool AHALF, bool CHALF>
__global__ __launch_bounds__(512, 1) void gemm_f16_kernel(
    const void* __restrict__ Av, const __half* __restrict__ Wt,
    const float* __restrict__ bias, void* __restrict__ Cv, int N)
{
    extern __shared__ char smem[];
    const uint32_t wBase = ((uint32_t)__cvta_generic_to_shared(smem) + 127) & ~127u;
    const uint32_t aBase = wBase + 24576;

    const int t    = threadIdx.x;
    const int bm   = blockIdx.y, bn = blockIdx.x;
    const int lane = t & 31, warp = t >> 5;
    const int wm   = warp >> 1;      // 0..7 : 32-row strip of 256
    const int wnn  = warp & 1;       // 0..1 : 64-col strip
    const int g    = lane >> 2;
    const int tq   = lane & 3;
    const int l15  = lane & 15, lhi = lane >> 4;

    // A mapping: row = t>>1 (0..255), k16-block akb = t&1
    const int arow = t >> 1, akb = t & 1;
    const int aSw  = (arow >> 1) & 3;
    size_t aoff;
    if (GATHER) {
        const int r    = bm * 256 + arow;
        const int wwin = r >> 6, p = r & 63;
        const int b    = wwin >> 8, widx = wwin & 255;
        const int wy   = widx >> 4, wx = widx & 15;
        const int py   = wy * 8 + (p >> 3);
        const int px   = wx * 8 + (p & 7);
        aoff = (((size_t)b * IMGH + py) * IMGW + px) * DIM;
    } else {
        aoff = (size_t)(bm * 256 + arow) * DIM;
    }
    const float*  ArowF = (const float*)Av + aoff;
    const __half* ArowH = (const __half*)Av + aoff;

    // W mapping: row wn_ = t>>2 (0..127), 16B chunk wc = t&3
    const int wn_ = t >> 2, wc = t & 3;
    const int wSw = (wn_ >> 1) & 3;
    const __half* Wrow = Wt + (size_t)(bn * 128 + wn_) * DIM;

    // ldsm lane addresses (offsets within a slot)
    uint32_t aRowO[2]; int aS[2];
    #pragma unroll
    for (int mi = 0; mi < 2; mi++) {
        int row = wm * 32 + mi * 16 + l15;
        aRowO[mi] = (uint32_t)row * 64;
        aS[mi]    = (row >> 1) & 3;
    }
    uint32_t bRowO[4]; int bS[4];
    #pragma unroll
    for (int nt = 0; nt < 4; nt++) {
        int row = wnn * 64 + nt * 16 + l15;
        bRowO[nt] = (uint32_t)row * 64;
        bS[nt]    = (row >> 1) & 3;
    }

    float acc[2][8][4];
    #pragma unroll
    for (int mi = 0; mi < 2; mi++)
        #pragma unroll
        for (int ni = 0; ni < 8; ni++)
            #pragma unroll
            for (int j = 0; j < 4; j++) acc[mi][ni][j] = 0.f;

    uint32_t apk[8];   // fp32-A register path

    auto issueW = [&](int it) {
        const int slot = it % 3;
        CP_ASYNC16(wBase + (uint32_t)slot * 8192 + (uint32_t)wn_ * 64
                   + (uint32_t)(((wc ^ wSw) << 4)),
                   Wrow + it * 32 + wc * 8);
    };
    auto issueA = [&](int it) {     // AHALF only
        const int slot = it % 3;
        const __half* src = ArowH + it * 32;
        #pragma unroll
        for (int j = 0; j < 2; j++) {
            const int c = 2 * akb + j;
            CP_ASYNC16(aBase + (uint32_t)slot * 16384 + (uint32_t)arow * 64
                       + (uint32_t)(((c ^ aSw) << 4)), src + c * 8);
        }
    };
    auto loadA = [&](int it) {
        const float* ap = ArowF + it * 32 + akb * 16;
        #pragma unroll
        for (int j = 0; j < 4; j++) {
            float4 v = *(const float4*)(ap + j * 4);
            apk[2*j]   = pkh2(v.x, v.y);
            apk[2*j+1] = pkh2(v.z, v.w);
        }
    };
    auto storeA = [&](int slot) {
        const uint32_t dst = aBase + (uint32_t)slot * 16384 + (uint32_t)arow * 64;
        const int c0 = 2 * akb, c1 = 2 * akb + 1;
        asm volatile("st.shared.v4.b32 [%0], {%1,%2,%3,%4};"
                     :: "r"(dst + (uint32_t)(((c0 ^ aSw) << 4))),
                        "r"(apk[0]), "r"(apk[1]), "r"(apk[2]), "r"(apk[3]) : "memory");
        asm volatile("st.shared.v4.b32 [%0], {%1,%2,%3,%4};"
                     :: "r"(dst + (uint32_t)(((c1 ^ aSw) << 4))),
                        "r"(apk[4]), "r"(apk[5]), "r"(apk[6]), "r"(apk[7]) : "memory");
    };

    // ---- prologue: stages 0,1 ----
    if (AHALF) { issueA(0); }
    issueW(0); CP_COMMIT();
    if (AHALF) { issueA(1); }
    issueW(1); CP_COMMIT();
    if (!AHALF) { loadA(0); storeA(0); }
    CP_WAIT1();
    __syncthreads();

    for (int it = 0; it < 8; it++) {
        const uint32_t aOff = AHALF ? (uint32_t)(it % 3) * 16384
                                    : (uint32_t)(it & 1) * 16384;
        const uint32_t wOff = (uint32_t)(it % 3) * 8192;

        if (!AHALF && it < 7) loadA(it + 1);
        if (it < 6) {
            if (AHALF) issueA(it + 2);
            issueW(it + 2);
            CP_COMMIT();
        }

        #pragma unroll
        for (int kb = 0; kb < 2; kb++) {
            const int kc = 2 * kb + lhi;
            uint32_t a[2][4];
            #pragma unroll
            for (int mi = 0; mi < 2; mi++)
                ldsm_x4(a[mi][0], a[mi][1], a[mi][2], a[mi][3],
                        aBase + aOff + aRowO[mi] + (uint32_t)(((kc ^ aS[mi]) << 4)));
            uint32_t b[4][4];
            #pragma unroll
            for (int nt = 0; nt < 4; nt++)
                ldsm_x4(b[nt][0], b[nt][1], b[nt][2], b[nt][3],
                        wBase + wOff + bRowO[nt] + (uint32_t)(((kc ^ bS[nt]) << 4)));
            #pragma unroll
            for (int mi = 0; mi < 2; mi++)
                #pragma unroll
                for (int nt = 0; nt < 4; nt++) {
                    mma_f16(acc[mi][2*nt],   a[mi][0], a[mi][1], a[mi][2], a[mi][3],
                            b[nt][0], b[nt][2]);
                    mma_f16(acc[mi][2*nt+1], a[mi][0], a[mi][1], a[mi][2], a[mi][3],
                            b[nt][1], b[nt][3]);
                }
        }

        if (!AHALF && it < 7) storeA((it + 1) & 1);
        if (it < 6)       { CP_WAIT1(); }
        else if (it == 6) { CP_WAIT0(); }
        __syncthreads();
    }

    // ---- epilogue ----
    #pragma unroll
    for (int mi = 0; mi < 2; mi++) {
        const int r0 = bm * 256 + wm * 32 + mi * 16 + g;
        #pragma unroll
        for (int ni = 0; ni < 8; ni++) {
            const int col = bn * 128 + wnn * 64 + ni * 8 + 2 * tq;
            float2 bv = *(const float2*)(bias + col);
            float c0 = acc[mi][ni][0] + bv.x, c1 = acc[mi][ni][1] + bv.y;
            float c2 = acc[mi][ni][2] + bv.x, c3 = acc[mi][ni][3] + bv.y;
            if (CHALF) {
                __half* C = (__half*)Cv;
                *(uint32_t*)(C + (size_t)r0 * N + col)       = pkh2(c0, c1);
                *(uint32_t*)(C + (size_t)(r0 + 8) * N + col) = pkh2(c2, c3);
            } else {
                float* C = (float*)Cv;
                *(float2*)(C + (size_t)r0 * N + col)       = make_float2(c0, c1);
                *(float2*)(C + (size_t)(r0 + 8) * N + col) = make_float2(c2, c3);
            }
        }
    }
}

// ---------------------------------------------------------------------------
// Attention (unchanged from R15/R16): row-major padded staging + ldmatrix.
// ---------------------------------------------------------------------------
#define QSTR 40
__global__ __launch_bounds__(256) void attn_mma_kernel()
{
    __shared__ __half Qs[256 * QSTR];
    __shared__ __half Ks[64 * QSTR];
    __shared__ __half Vs[64 * QSTR];
    __shared__ __half Bs_h[64][66];

    const int blk = blockIdx.x;
    const int win = blk >> 3;
    const int h   = blk & 7;
    const int t   = threadIdx.x;
    const int lane = t & 31, warp = t >> 5;
    const int g   = lane >> 2;
    const int tq  = lane & 3;
    const int l15 = lane & 15, lhi = lane >> 4;
    const int l7  = lane & 7,  l8  = (lane >> 3) & 1;

    const uint32_t qBase = (uint32_t)__cvta_generic_to_shared(Qs);
    const uint32_t kBase = (uint32_t)__cvta_generic_to_shared(Ks);
    const uint32_t vBase = (uint32_t)__cvta_generic_to_shared(Vs);

    {
        const uint4* qp4 = (const uint4*)(g_q + ((size_t)(win * NQ + t)) * DIM + h * HD);
        const uint32_t dst = qBase + (uint32_t)t * 80;
        uint4 u0 = qp4[0], u1 = qp4[1], u2 = qp4[2], u3 = qp4[3];
        asm volatile("st.shared.v4.b32 [%0], {%1,%2,%3,%4};" :: "r"(dst),      "r"(u0.x),"r"(u0.y),"r"(u0.z),"r"(u0.w) : "memory");
        asm volatile("st.shared.v4.b32 [%0], {%1,%2,%3,%4};" :: "r"(dst + 16), "r"(u1.x),"r"(u1.y),"r"(u1.z),"r"(u1.w) : "memory");
        asm volatile("st.shared.v4.b32 [%0], {%1,%2,%3,%4};" :: "r"(dst + 32), "r"(u2.x),"r"(u2.y),"r"(u2.z),"r"(u2.w) : "memory");
        asm volatile("st.shared.v4.b32 [%0], {%1,%2,%3,%4};" :: "r"(dst + 48), "r"(u3.x),"r"(u3.y),"r"(u3.z),"r"(u3.w) : "memory");
    }
    if (t < 128) {
        const int key = t & 63;
        const size_t src = (size_t)(win * WS2 + key) * 512 + ((t < 64) ? 0 : (size_t)DIM) + h * HD;
        const uint4* p4 = (const uint4*)(g_kv + src);
        const uint32_t dst = ((t < 64) ? kBase : vBase) + (uint32_t)key * 80;
        uint4 u0 = p4[0], u1 = p4[1], u2 = p4[2], u3 = p4[3];
        asm volatile("st.shared.v4.b32 [%0], {%1,%2,%3,%4};" :: "r"(dst),      "r"(u0.x),"r"(u0.y),"r"(u0.z),"r"(u0.w) : "memory");
        asm volatile("st.shared.v4.b32 [%0], {%1,%2,%3,%4};" :: "r"(dst + 16), "r"(u1.x),"r"(u1.y),"r"(u1.z),"r"(u1.w) : "memory");
        asm volatile("st.shared.v4.b32 [%0], {%1,%2,%3,%4};" :: "r"(dst + 32), "r"(u2.x),"r"(u2.y),"r"(u2.z),"r"(u2.w) : "memory");
        asm volatile("st.shared.v4.b32 [%0], {%1,%2,%3,%4};" :: "r"(dst + 48), "r"(u3.x),"r"(u3.y),"r"(u3.z),"r"(u3.w) : "memory");
    }
    {
        const __half* gb = g_bias + h * 4096;
        #pragma unroll
        for (int i = 0; i < 2; i++) {
            int idx = t + i * 256;
            int qp = idx >> 3, c8 = (idx & 7) * 8;
            uint4 u = *(const uint4*)(gb + qp * 64 + c8);
            uint32_t* dst = (uint32_t*)((char*)&Bs_h[qp][0] + c8 * 2);
            dst[0] = u.x; dst[1] = u.y; dst[2] = u.z; dst[3] = u.w;
        }
    }
    __syncthreads();

    float acc[2][8][4];
    #pragma unroll
    for (int mi = 0; mi < 2; mi++)
        #pragma unroll
        for (int ni = 0; ni < 8; ni++)
            #pragma unroll
            for (int j = 0; j < 4; j++) acc[mi][ni][j] = 0.f;

    #pragma unroll
    for (int kb = 0; kb < 2; kb++) {
        const uint32_t cOff = (uint32_t)(2 * kb + lhi) * 16;
        uint32_t a[2][4];
        #pragma unroll
        for (int mi = 0; mi < 2; mi++)
            ldsm_x4(a[mi][0], a[mi][1], a[mi][2], a[mi][3],
                    qBase + (uint32_t)(warp * 32 + mi * 16 + l15) * 80 + cOff);
        uint32_t b[4][4];
        #pragma unroll
        for (int ng = 0; ng < 4; ng++)
            ldsm_x4(b[ng][0], b[ng][1], b[ng][2], b[ng][3],
                    kBase + (uint32_t)(ng * 16 + l15) * 80 + cOff);
        #pragma unroll
        for (int mi = 0; mi < 2; mi++)
            #pragma unroll
            for (int ng = 0; ng < 4; ng++) {
                mma_f16(acc[mi][2*ng],   a[mi][0], a[mi][1], a[mi][2], a[mi][3],
                        b[ng][0], b[ng][2]);
                mma_f16(acc[mi][2*ng+1], a[mi][0], a[mi][1], a[mi][2], a[mi][3],
                        b[ng][1], b[ng][3]);
            }
    }

    const float scale = 0.17677669529663687f;
    float inv_[2][2];
    #pragma unroll
    for (int mi = 0; mi < 2; mi++) {
        const int rA = warp * 32 + mi * 16 + g;
        const int qA = rA & 63, qB = (rA + 8) & 63;
        float mA = -1e30f, mB = -1e30f;
        #pragma unroll
        for (int ni = 0; ni < 8; ni++) {
            const int col = ni * 8 + 2 * tq;
            float2 bA = __half22float2(*(const __half2*)&Bs_h[qA][col]);
            float2 bB = __half22float2(*(const __half2*)&Bs_h[qB][col]);
            acc[mi][ni][0] = acc[mi][ni][0] * scale + bA.x;
            acc[mi][ni][1] = acc[mi][ni][1] * scale + bA.y;
            acc[mi][ni][2] = acc[mi][ni][2] * scale + bB.x;
            acc[mi][ni][3] = acc[mi][ni][3] * scale + bB.y;
            mA = fmaxf(mA, fmaxf(acc[mi][ni][0], acc[mi][ni][1]));
            mB = fmaxf(mB, fmaxf(acc[mi][ni][2], acc[mi][ni][3]));
        }
        mA = fmaxf(mA, __shfl_xor_sync(0xffffffff, mA, 1));
        mA = fmaxf(mA, __shfl_xor_sync(0xffffffff, mA, 2));
        mB = fmaxf(mB, __shfl_xor_sync(0xffffffff, mB, 1));
        mB = fmaxf(mB, __shfl_xor_sync(0xffffffff, mB, 2));
        float sA = 0.f, sB = 0.f;
        #pragma unroll
        for (int ni = 0; ni < 8; ni++) {
            float e0 = __expf(acc[mi][ni][0] - mA);
            float e1 = __expf(acc[mi][ni][1] - mA);
            float e2 = __expf(acc[mi][ni][2] - mB);
            float e3 = __expf(acc[mi][ni][3] - mB);
            acc[mi][ni][0] = e0; acc[mi][ni][1] = e1;
            acc[mi][ni][2] = e2; acc[mi][ni][3] = e3;
            sA += e0 + e1; sB += e2 + e3;
        }
        sA += __shfl_xor_sync(0xffffffff, sA, 1);
        sA += __shfl_xor_sync(0xffffffff, sA, 2);
        sB += __shfl_xor_sync(0xffffffff, sB, 1);
        sB += __shfl_xor_sync(0xffffffff, sB, 2);
        inv_[mi][0] = 1.f / sA;
        inv_[mi][1] = 1.f / sB;
    }

    float o[2][4][4];
    #pragma unroll
    for (int mi = 0; mi < 2; mi++)
        #pragma unroll
        for (int ni = 0; ni < 4; ni++)
            #pragma unroll
            for (int j = 0; j < 4; j++) o[mi][ni][j] = 0.f;

    #pragma unroll
    for (int kb = 0; kb < 4; kb++) {
        uint32_t a0[2], a1[2], a2[2], a3[2];
        #pragma unroll
        for (int mi = 0; mi < 2; mi++) {
            a0[mi] = pkh2(acc[mi][2*kb][0],     acc[mi][2*kb][1]);
            a1[mi] = pkh2(acc[mi][2*kb][2],     acc[mi][2*kb][3]);
            a2[mi] = pkh2(acc[mi][2*kb+1][0],   acc[mi][2*kb+1][1]);
            a3[mi] = pkh2(acc[mi][2*kb+1][2],   acc[mi][2*kb+1][3]);
        }
        const uint32_t vRow = vBase + (uint32_t)(kb * 16 + l8 * 8 + l7) * 80;
        #pragma unroll
        for (int ndp = 0; ndp < 2; ndp++) {
            uint32_t b0, b1, b2, b3;
            ldsm_x4_t(b0, b1, b2, b3, vRow + (uint32_t)(ndp * 2 + lhi) * 16);
            #pragma unroll
            for (int mi = 0; mi < 2; mi++) {
                mma_f16(o[mi][2*ndp],   a0[mi], a1[mi], a2[mi], a3[mi], b0, b1);
                mma_f16(o[mi][2*ndp+1], a0[mi], a1[mi], a2[mi], a3[mi], b2, b3);
            }
        }
    }

    #pragma unroll
    for (int mi = 0; mi < 2; mi++) {
        const int r = win * NQ + warp * 32 + mi * 16 + g;
        const float ivA = inv_[mi][0], ivB = inv_[mi][1];
        #pragma unroll
        for (int ni = 0; ni < 4; ni++) {
            const int col = h * HD + ni * 8 + 2 * tq;
            *(uint32_t*)(g_att + (size_t)r * DIM + col) =
                pkh2(o[mi][ni][0] * ivA, o[mi][ni][1] * ivA);
            *(uint32_t*)(g_att + (size_t)(r + 8) * DIM + col) =
                pkh2(o[mi][ni][2] * ivB, o[mi][ni][3] * ivB);
        }
    }
}

// ---------------------------------------------------------------------------
extern "C" void kernel_launch(void* const* d_in, const int* in_sizes, int n_in,
                              void* d_out, int out_size)
{
    const float* gauss = (const float*)d_in[0];
    const float* img   = (const float*)d_in[1];
    const float* btab  = (const float*)d_in[2];
    const float* Wq    = (const float*)d_in[3];
    const float* bq    = (const float*)d_in[4];
    const float* Wkv   = (const float*)d_in[5];
    const float* bkv   = (const float*)d_in[6];
    const float* Wp    = (const float*)d_in[7];
    const float* bp    = (const float*)d_in[8];
    float* out = (float*)d_out;

    void* pq = nullptr;   cudaGetSymbolAddress(&pq, g_q);
    void* pkv = nullptr;  cudaGetSymbolAddress(&pkv, g_kv);
    void* pa = nullptr;   cudaGetSymbolAddress(&pa, g_att);
    void* pwt = nullptr;  cudaGetSymbolAddress(&pwt, g_wt);
    const __half* wt = (const __half*)pwt;

    cudaFuncSetAttribute(gemm_f16_kernel<false, false, true>,
                         cudaFuncAttributeMaxDynamicSharedMemorySize, GEMM_SMEM);
    cudaFuncSetAttribute(gemm_f16_kernel<true, false, true>,
                         cudaFuncAttributeMaxDynamicSharedMemorySize, GEMM_SMEM);
    cudaFuncSetAttribute(gemm_f16_kernel<false, true, false>,
                         cudaFuncAttributeMaxDynamicSharedMemorySize, GEMM_SMEM);

    // 0) prep: bias table + transposed fp16 weights
    bias_prep_kernel<<<HEADS, 256>>>(btab);
    w_prep_kernel<<<1024, 256>>>(Wq, Wkv, Wp);
    // 1) Q projection: fp32 A -> fp16 C
    gemm_f16_kernel<false, false, true>
        <<<dim3(DIM / 128, ROWS_Q / 256), 512, GEMM_SMEM>>>(gauss, wt, bq, pq, DIM);
    // 2) KV projection (window gather): fp32 A -> fp16 C
    gemm_f16_kernel<true, false, true>
        <<<dim3((2 * DIM) / 128, ROWS_KV / 256), 512, GEMM_SMEM>>>(img, wt + 256 * DIM, bkv, pkv, 2 * DIM);
    // 3) Attention (ldmatrix staging, register-resident P)
    attn_mma_kernel<<<BW * HEADS, 256>>>();
    // 4) Output projection: fp16 A (cp.async) -> fp32 C (d_out)
    gemm_f16_kernel<false, true, false>
        <<<dim3(DIM / 128, ROWS_Q / 256), 512, GEMM_SMEM>>>(pa, wt + 768 * DIM, bp, out, DIM);
}